// round 8
// baseline (speedup 1.0000x reference)
#include <cuda_runtime.h>
#include <cstdint>
#include <cstddef>

// STPCell fused kernel, R7: grid-matched persistent work-list (592 CTAs = 4/SM
// exactly), unit = (j, 8 batches) -> 4096 units, static stride-592 assignment
// (1.2% tail vs 13.5% wave quantization). Barrier-free cp.async ring (ND=5)
// streams X/U continuously ACROSS unit boundaries.

#define HH    1024
#define IND   512
#define BB    32
#define NSM   148
#define NCTA  (4 * NSM)                 // 592
#define NUNIT 4096                      // 1024 j * 4 b-groups
#define BPU   8                         // batches per unit
#define ND    5                         // ring stages (prefetch distance 4)
#define BSTR  ((size_t)HH * HH * 4)     // bytes between batches of X/U

__device__ __forceinline__ float sigf(float v) {
    return 1.0f / (1.0f + __expf(-v));
}

__device__ __forceinline__ void cp16(uint32_t saddr, const void* gaddr) {
    asm volatile("cp.async.cg.shared.global [%0], [%1], 16;\n"
                 :: "r"(saddr), "l"(gaddr));
}
#define CP_COMMIT() asm volatile("cp.async.commit_group;\n" ::: "memory")
#define CP_WAIT(n)  asm volatile("cp.async.wait_group %0;\n" :: "n"(n) : "memory")

__global__ __launch_bounds__(256, 4) void stp_main(
    const float* __restrict__ x_in,   // (IN, B)
    const float* __restrict__ h,      // (B, H)
    const float* __restrict__ X,      // (B, H, H)
    const float* __restrict__ U,      // (B, H, H)
    const float* __restrict__ c_x,    // (H, H)
    const float* __restrict__ c_u,    // (H, H)
    const float* __restrict__ c_U,    // (H, H)
    const float* __restrict__ c_h,    // (H, 1)
    const float* __restrict__ w,      // (H, H)
    const float* __restrict__ p,      // (H, IN)
    const float* __restrict__ bias,   // (H, 1)
    float* __restrict__ out)          // (B, H)
{
    const int cta  = blockIdx.x;
    const int tid  = threadIdx.x;
    const int lane = tid & 31;
    const int warp = tid >> 5;
    const size_t toff = (size_t)tid * 16;    // byte offset of this thread's float4

    __shared__ float4 xst[ND][256];          // 20 KB
    __shared__ float4 ust[ND][256];          // 20 KB
    __shared__ float  sbuf[32][BPU];         // px partials
    __shared__ float  sred[8][BPU];          // epilogue partials
    __shared__ float  px_s[BPU];
    __shared__ float  hj_s[BPU];

    const float4* __restrict__ h4 = reinterpret_cast<const float4*>(h);
    const char*  Xc = reinterpret_cast<const char*>(X);
    const char*  Uc = reinterpret_cast<const char*>(U);
    const uint32_t xs0 = (uint32_t)__cvta_generic_to_shared(&xst[0][tid]);
    const uint32_t us0 = (uint32_t)__cvta_generic_to_shared(&ust[0][tid]);

    const int T = (NUNIT - 1 - cta) / NCTA + 1;   // units for this CTA (6 or 7)

    // ---- unit 0 identity ----
    int u0 = cta;
    int j  = u0 >> 2;
    int bb = (u0 & 3) * BPU;

    // ---- prefetch tracker: next seq position to fetch is (pt, pq) ----
    int pt = 0, pq = ND - 1;                 // prologue fills q = 0..ND-2
    int pj = j, pbb = bb;

    // ---- prologue ring fill: batches bb..bb+ND-2 of unit 0 ----
    {
        size_t rowoff = (size_t)j * 4096 + toff;
        #pragma unroll
        for (int s = 0; s < ND - 1; ++s) {
            size_t a = (size_t)(bb + s) * BSTR + rowoff;
            cp16(xs0 + s * 4096, Xc + a);
            cp16(us0 + s * 4096, Uc + a);
            CP_COMMIT();
        }
    }
    int rstage = 0, wstage = ND - 1;

    // ---- h pipeline (distance 2), continuous across units ----
    float4 h0 = __ldg(h4 + (bb + 0) * (HH / 4) + tid);
    float4 h1 = __ldg(h4 + (bb + 1) * (HH / 4) + tid);

    // ================= unit loop =================
    #pragma unroll 1
    for (int t = 0; t < T; ++t) {
        // next unit identity (for cross-unit prefetch + h pipeline)
        int bbn = bb, jn = j;
        if (t + 1 < T) {
            int un = cta + (t + 1) * NCTA;
            jn  = un >> 2;
            bbn = (un & 3) * BPU;
        }
        (void)jn;

        __syncthreads();   // protect smem (sred/px_s/hj_s/sbuf) from prior unit

        // per-unit constants
        const int rowP = j * (HH / 4) + tid;
        const float4 cxv = __ldg(reinterpret_cast<const float4*>(c_x) + rowP);
        const float4 cuv = __ldg(reinterpret_cast<const float4*>(c_u) + rowP);
        const float4 cUv = __ldg(reinterpret_cast<const float4*>(c_U) + rowP);
        const float4 wv  = __ldg(reinterpret_cast<const float4*>(w)   + rowP);

        if (tid < BPU) hj_s[tid] = h[(bb + tid) * HH + j];

        // (p @ x)[j, bb..bb+7]: 32 segments of 16 i, b = tid & 7
        {
            const int seg = tid >> 3;
            const int bl  = tid & 7;
            const float* prow = p + j * IND;
            float a = 0.0f;
            #pragma unroll 8
            for (int i = seg * 16; i < seg * 16 + 16; ++i)
                a = fmaf(prow[i], x_in[i * BB + bb + bl], a);
            sbuf[seg][bl] = a;
        }
        __syncthreads();
        if (tid < BPU) {
            float s = 0.0f;
            #pragma unroll
            for (int q = 0; q < 32; ++q) s += sbuf[q][tid];
            px_s[tid] = s;
        }

        // per-(j,k) sigmoid constants
        float4 zx, zu, uc;
        zx.x = 0.001f + 0.099f * sigf(cxv.x);
        zx.y = 0.001f + 0.099f * sigf(cxv.y);
        zx.z = 0.001f + 0.099f * sigf(cxv.z);
        zx.w = 0.001f + 0.099f * sigf(cxv.w);
        zu.x = 0.001f + 0.099f * sigf(cuv.x);
        zu.y = 0.001f + 0.099f * sigf(cuv.y);
        zu.z = 0.001f + 0.099f * sigf(cuv.z);
        zu.w = 0.001f + 0.099f * sigf(cuv.w);
        uc.x = 0.9f * sigf(cUv.x);
        uc.y = 0.9f * sigf(cUv.y);
        uc.z = 0.9f * sigf(cUv.z);
        uc.w = 0.9f * sigf(cUv.w);

        // ---- 8 batches: 2 groups of 4 with deferred shuffle reduction ----
        #pragma unroll 1
        for (int g = 0; g < 2; ++g) {
            float a[4] = {0.0f, 0.0f, 0.0f, 0.0f};

            #pragma unroll
            for (int qq = 0; qq < 4; ++qq) {
                const int q = g * 4 + qq;

                CP_WAIT(ND - 2);
                const float4 x0 = xst[rstage][tid];
                const float4 u0 = ust[rstage][tid];
                rstage = (rstage + 1 == ND) ? 0 : rstage + 1;

                // prefetch seq position (pt, pq) -- may be in the next unit
                {
                    size_t a2 = (size_t)(pbb + pq) * BSTR
                              + (size_t)pj * 4096 + toff;
                    cp16(xs0 + wstage * 4096, Xc + a2);
                    cp16(us0 + wstage * 4096, Uc + a2);
                    CP_COMMIT();
                    wstage = (wstage + 1 == ND) ? 0 : wstage + 1;
                    if (++pq == BPU) {
                        pq = 0;
                        ++pt;
                        if (pt < T) {
                            int un = cta + pt * NCTA;
                            pj  = un >> 2;
                            pbb = (un & 3) * BPU;
                        }  // else: clamp (harmless refetch of last unit)
                    }
                }

                // h prefetch at distance 2 (cross-unit aware)
                int nb = (q + 2 < BPU) ? (bb + q + 2) : (bbn + q + 2 - BPU);
                float4 hn = __ldg(h4 + nb * (HH / 4) + tid);

                const float hj = hj_s[q];

                // X_new = fma(z_x, 1-X, X) - U*(X*hj)
                // U_new = Ucap*(z_u+hj) + U*((1-z_u)-Ucap*hj), clip [Ucap,1]
                // a[qq] += (w * U_new * X_new) * h[b,k]
                #define STP_PROC(C)                                         \
                {                                                           \
                    float xx = x0.C, uu = u0.C;                             \
                    float xnew = fmaf(zx.C, 1.0f - xx, xx);                 \
                    xnew = fmaf(-uu, xx * hj, xnew);                        \
                    float addu = uc.C * (zu.C + hj);                        \
                    float cofu = fmaf(-uc.C, hj, 1.0f - zu.C);              \
                    float unew = fmaf(uu, cofu, addu);                      \
                    unew = fminf(fmaxf(unew, uc.C), 1.0f);                 \
                    a[qq] = fmaf(wv.C * unew * xnew, h0.C, a[qq]);          \
                }
                STP_PROC(x) STP_PROC(y) STP_PROC(z) STP_PROC(w)
                #undef STP_PROC

                h0 = h1; h1 = hn;
            }

            // 4 interleaved shuffle trees
            #pragma unroll
            for (int o = 16; o > 0; o >>= 1) {
                a[0] += __shfl_xor_sync(0xffffffffu, a[0], o);
                a[1] += __shfl_xor_sync(0xffffffffu, a[1], o);
                a[2] += __shfl_xor_sync(0xffffffffu, a[2], o);
                a[3] += __shfl_xor_sync(0xffffffffu, a[3], o);
            }
            if (lane == 0) {
                sred[warp][g * 4 + 0] = a[0];
                sred[warp][g * 4 + 1] = a[1];
                sred[warp][g * 4 + 2] = a[2];
                sred[warp][g * 4 + 3] = a[3];
            }
        }
        __syncthreads();

        // ---- finalize this unit: thread q (< 8) writes out[bb+q, j] ----
        if (tid < BPU) {
            const int b = bb + tid;
            float rec = 0.0f;
            #pragma unroll
            for (int q = 0; q < 8; ++q) rec += sred[q][tid];

            float pre = rec + px_s[tid] + __ldg(bias + j);
            float zh  = 0.5f * sigf(__ldg(c_h + j));     // E_H = 0.5
            float hbj = hj_s[tid];
            out[b * HH + j] = fmaf(zh, sigf(pre) - hbj, hbj);
        }

        // advance current-unit identity
        j = jn; bb = bbn;
    }

    CP_WAIT(0);   // drain clamped tail prefetches before exit
}

// ---------------------------------------------------------------------------
// Inputs (metadata order): x, h, X, U, c_x, c_u, c_U, c_h, w, p, b
// ---------------------------------------------------------------------------
extern "C" void kernel_launch(void* const* d_in, const int* in_sizes, int n_in,
                              void* d_out, int out_size)
{
    const float* x_in = (const float*)d_in[0];
    const float* h    = (const float*)d_in[1];
    const float* X    = (const float*)d_in[2];
    const float* U    = (const float*)d_in[3];
    const float* c_x  = (const float*)d_in[4];
    const float* c_u  = (const float*)d_in[5];
    const float* c_U  = (const float*)d_in[6];
    const float* c_h  = (const float*)d_in[7];
    const float* w    = (const float*)d_in[8];
    const float* p    = (const float*)d_in[9];
    const float* bias = (const float*)d_in[10];
    float* out = (float*)d_out;

    stp_main<<<NCTA, 256>>>(x_in, h, X, U, c_x, c_u, c_U, c_h, w, p, bias, out);
}